// round 6
// baseline (speedup 1.0000x reference)
#include <cuda_runtime.h>

// MicroGPT forward, sm_103a. Fixed shapes.
#define NB  16
#define NT  2048
#define NC  16
#define NH  2
#define NHS 8
#define NL  2
#define NV  256
#define NTOK (NB*NT)
#define EPSF 1e-5f
// (1/sqrt(HS)) * log2(e): q pre-scaled so softmax uses ex2 directly
#define QSCALE 0.5100700982280911f

typedef unsigned long long u64;

// Scratch (device globals; no dynamic allocation allowed)
__device__ float g_x[NTOK*NC];
__device__ float g_q[NB*NH*NT*NHS];
__device__ float g_k[NB*NH*NT*NHS];
__device__ float g_v[NB*NH*NT*NHS];
__device__ float g_o[NB*NH*NT*NHS];

__device__ __forceinline__ float ex2f(float x){
    float y; asm("ex2.approx.f32 %0, %1;" : "=f"(y) : "f"(x)); return y;
}
__device__ __forceinline__ u64 fma2(u64 a, u64 b, u64 c){
    u64 d; asm("fma.rn.f32x2 %0, %1, %2, %3;" : "=l"(d) : "l"(a), "l"(b), "l"(c)); return d;
}
__device__ __forceinline__ u64 mul2(u64 a, u64 b){
    u64 d; asm("mul.rn.f32x2 %0, %1, %2;" : "=l"(d) : "l"(a), "l"(b)); return d;
}
__device__ __forceinline__ u64 add2(u64 a, u64 b){
    u64 d; asm("add.rn.f32x2 %0, %1, %2;" : "=l"(d) : "l"(a), "l"(b)); return d;
}
__device__ __forceinline__ u64 pack2(float lo, float hi){
    u64 r; asm("mov.b64 %0, {%1, %2};" : "=l"(r) : "f"(lo), "f"(hi)); return r;
}
__device__ __forceinline__ float2 unpack2(u64 v){
    float lo, hi; asm("mov.b64 {%0, %1}, %2;" : "=f"(lo), "=f"(hi) : "l"(v));
    return make_float2(lo, hi);
}

// ---------------------------------------------------------------------------
// 1) h = LN1(x); q,k,v = h @ W (q pre-scaled). Layer 0 fuses the embedding.
//    One thread per (token, head): head = gid>>15 so stores stay coalesced.
// ---------------------------------------------------------------------------
__global__ void __launch_bounds__(128) qkv_kernel(const float* __restrict__ wq,
                           const float* __restrict__ wk,
                           const float* __restrict__ wv,
                           const float* __restrict__ g1,
                           const float* __restrict__ b1,
                           const int*   __restrict__ idx,
                           const float* __restrict__ te,
                           const float* __restrict__ pe,
                           int fuse_embed){
    __shared__ float sq[NH*NC*NHS], sk[NH*NC*NHS], sv[NH*NC*NHS];
    __shared__ float sg[NC], sb[NC];
    int tid = threadIdx.x;
    for (int i=tid; i<NH*NC*NHS; i+=128){ sq[i]=wq[i]; sk[i]=wk[i]; sv[i]=wv[i]; }
    if (tid < NC){ sg[tid]=g1[tid]; sb[tid]=b1[tid]; }
    __syncthreads();

    int gid  = blockIdx.x*128 + tid;
    int head = gid >> 15;              // 0 or 1
    int tok  = gid & (NTOK-1);
    int b = tok >> 11;
    int t = tok & (NT-1);

    float xr[NC];
    if (fuse_embed){
        int id = idx[tok];
        const float4* t4 = (const float4*)te + id*4;
        const float4* p4 = (const float4*)pe + t*4;
        #pragma unroll
        for (int k=0;k<4;k++){
            float4 aa=t4[k], bb=p4[k];
            float4 r = make_float4(aa.x+bb.x, aa.y+bb.y, aa.z+bb.z, aa.w+bb.w);
            if (head == 0) ((float4*)g_x)[(size_t)tok*4 + k] = r;  // write once
            xr[4*k]=r.x; xr[4*k+1]=r.y; xr[4*k+2]=r.z; xr[4*k+3]=r.w;
        }
    } else {
        const float4* x4 = (const float4*)g_x + (size_t)tok*4;
        #pragma unroll
        for (int k=0;k<4;k++){
            float4 v=x4[k];
            xr[4*k]=v.x; xr[4*k+1]=v.y; xr[4*k+2]=v.z; xr[4*k+3]=v.w;
        }
    }

    float m=0.f;
    #pragma unroll
    for (int c=0;c<NC;c++) m += xr[c];
    m *= (1.f/NC);
    float var=0.f;
    #pragma unroll
    for (int c=0;c<NC;c++){ float d=xr[c]-m; var += d*d; }
    var *= (1.f/NC);
    float inv = rsqrtf(var + EPSF);
    float h[NC];
    #pragma unroll
    for (int c=0;c<NC;c++) h[c] = (xr[c]-m)*inv*sg[c] + sb[c];

    size_t obase = ((size_t)(b*NH+head)*NT + t)*NHS;
    const float* Wq = sq + head*NC*NHS;
    const float* Wk = sk + head*NC*NHS;
    const float* Wv = sv + head*NC*NHS;
    float aq[NHS], ak[NHS], av[NHS];
    #pragma unroll
    for (int s=0;s<NHS;s++){ aq[s]=0.f; ak[s]=0.f; av[s]=0.f; }
    #pragma unroll
    for (int c=0;c<NC;c++){
        float hc = h[c];
        #pragma unroll
        for (int s=0;s<NHS;s++){
            aq[s] += hc*Wq[c*NHS+s];
            ak[s] += hc*Wk[c*NHS+s];
            av[s] += hc*Wv[c*NHS+s];
        }
    }
    float4* qo = (float4*)(g_q + obase);
    float4* ko = (float4*)(g_k + obase);
    float4* vo = (float4*)(g_v + obase);
    qo[0] = make_float4(aq[0]*QSCALE, aq[1]*QSCALE, aq[2]*QSCALE, aq[3]*QSCALE);
    qo[1] = make_float4(aq[4]*QSCALE, aq[5]*QSCALE, aq[6]*QSCALE, aq[7]*QSCALE);
    ko[0] = make_float4(ak[0], ak[1], ak[2], ak[3]);
    ko[1] = make_float4(ak[4], ak[5], ak[6], ak[7]);
    vo[0] = make_float4(av[0], av[1], av[2], av[3]);
    vo[1] = make_float4(av[4], av[5], av[6], av[7]);
}

// ---------------------------------------------------------------------------
// 2) Causal attention. Single query per thread; 512-thread blocks.
//    Block (bh, y) quads own tiles {2y, 2y+1, 14-2y, 15-2y} (sum 34 units,
//    uniform per block AND per SMSP since warp w's quad = w>>2).
//    grid=(32,4) = 128 uniform blocks.
// ---------------------------------------------------------------------------
__global__ void __launch_bounds__(512) attn_kernel(){
    int bh   = blockIdx.x;
    int y    = blockIdx.y;              // 0..3
    int tid  = threadIdx.x;
    int quad = tid >> 7;                // 0..3
    int lane = tid & 127;

    int tq;
    switch (quad){
        case 0:  tq = 2*y;      break;
        case 1:  tq = 2*y+1;    break;
        case 2:  tq = 14-2*y;   break;
        default: tq = 15-2*y;   break;
    }
    int t = tq*128 + lane;

    const float4* kg = (const float4*)g_k + (size_t)bh*NT*2;
    const float4* vg = (const float4*)g_v + (size_t)bh*NT*2;

    const ulonglong2* qg = (const ulonglong2*)(g_q + ((size_t)bh*NT + t)*NHS);
    ulonglong2 qA = qg[0], qB = qg[1];
    u64 q01 = qA.x, q23 = qA.y, q45 = qB.x, q67 = qB.y;

    __shared__ ulonglong2 ks[256];   // 128 keys x 32B
    __shared__ ulonglong2 vs[256];

    float den = 0.f;
    u64 a0=0,a1=0,a2=0,a3=0;

    int ktmax = 15 - 2*y;
    for (int kt=0; kt<=ktmax; kt++){
        if (tid < 256) ((float4*)ks)[tid]     = kg[kt*256 + tid];
        else           ((float4*)vs)[tid-256] = vg[kt*256 + tid - 256];
        __syncthreads();

        if (kt <= tq){
            int jmax = (kt==tq) ? (lane+1) : 128;
            #pragma unroll 4
            for (int j=0; j<jmax; j++){
                ulonglong2 k0 = ks[2*j], k1 = ks[2*j+1];
                u64 s2 = mul2(q01, k0.x);
                s2 = fma2(q23, k0.y, s2);
                s2 = fma2(q45, k1.x, s2);
                s2 = fma2(q67, k1.y, s2);
                float2 f = unpack2(s2);
                float p = ex2f(f.x + f.y);
                den += p;
                u64 pp = pack2(p, p);
                ulonglong2 v0 = vs[2*j], v1 = vs[2*j+1];
                a0 = fma2(pp, v0.x, a0);
                a1 = fma2(pp, v0.y, a1);
                a2 = fma2(pp, v1.x, a2);
                a3 = fma2(pp, v1.y, a3);
            }
        }
        __syncthreads();
    }

    float id = 1.f/den;
    float2 r0=unpack2(a0), r1=unpack2(a1), r2=unpack2(a2), r3=unpack2(a3);
    float4* op = (float4*)(g_o + ((size_t)bh*NT + t)*NHS);
    op[0] = make_float4(r0.x*id, r0.y*id, r1.x*id, r1.y*id);
    op[1] = make_float4(r2.x*id, r2.y*id, r3.x*id, r3.y*id);
}

// ---------------------------------------------------------------------------
// 3) x += concat(o) @ Wo^T;  h = LN2(x);  x += relu(h @ W1^T) @ W2^T
//    Two threads per token (lane pair): each does 32 of the 64 hidden units,
//    lane^1 butterfly merges the deltas, stores split between the pair.
// ---------------------------------------------------------------------------
__global__ void __launch_bounds__(128) post_kernel(const float* __restrict__ wo,
                            const float* __restrict__ g2,
                            const float* __restrict__ b2,
                            const float* __restrict__ w1,
                            const float* __restrict__ w2){
    __shared__ __align__(16) float s_wo[NC*NC];
    __shared__ __align__(16) float s_w1[4*NC*NC];
    __shared__ __align__(16) float s_w2[4*NC*NC];   // [j][i] = w2[i][j]
    __shared__ float sg[NC], sb[NC];
    int tid = threadIdx.x;
    for (int i=tid; i<NC*NC; i+=128) s_wo[i] = wo[i];
    for (int i=tid; i<4*NC*NC; i+=128) s_w1[i] = w1[i];
    for (int idx=tid; idx<4*NC*NC; idx+=128){
        int j = idx >> 4, i = idx & 15;
        s_w2[idx] = w2[i*(4*NC) + j];
    }
    if (tid < NC){ sg[tid]=g2[tid]; sb[tid]=b2[tid]; }
    __syncthreads();

    int gid  = blockIdx.x*128 + tid;
    int half = gid & 1;
    int tok  = gid >> 1;
    int b = tok >> 11;
    int t = tok & (NT-1);

    // o16 packed as 8 u64
    u64 o2[8];
    {
        const ulonglong2* p0 = (const ulonglong2*)(g_o + ((size_t)(b*NH+0)*NT + t)*NHS);
        const ulonglong2* p1 = (const ulonglong2*)(g_o + ((size_t)(b*NH+1)*NT + t)*NHS);
        ulonglong2 u0=p0[0], u1=p0[1], u2=p1[0], u3=p1[1];
        o2[0]=u0.x; o2[1]=u0.y; o2[2]=u1.x; o2[3]=u1.y;
        o2[4]=u2.x; o2[5]=u2.y; o2[6]=u3.x; o2[7]=u3.y;
    }

    float xr[NC];
    {
        const float4* x4 = (const float4*)g_x + (size_t)tok*4;
        #pragma unroll
        for (int k=0;k<4;k++){
            float4 v=x4[k];
            xr[4*k]=v.x; xr[4*k+1]=v.y; xr[4*k+2]=v.z; xr[4*k+3]=v.w;
        }
    }

    // Wo projection + residual (f32x2) — duplicated across the pair
    #pragma unroll
    for (int i=0;i<NC;i++){
        const ulonglong2* wr = (const ulonglong2*)(s_wo + i*NC);
        ulonglong2 w0 = wr[0], w1r = wr[1];
        u64 s2 = mul2(o2[0], w0.x);
        s2 = fma2(o2[1], w0.y, s2);
        s2 = fma2(o2[2], w1r.x, s2);
        s2 = fma2(o2[3], w1r.y, s2);
        ulonglong2 w2r = wr[2], w3r = wr[3];
        s2 = fma2(o2[4], w2r.x, s2);
        s2 = fma2(o2[5], w2r.y, s2);
        s2 = fma2(o2[6], w3r.x, s2);
        s2 = fma2(o2[7], w3r.y, s2);
        float2 f = unpack2(s2);
        xr[i] += f.x + f.y;
    }

    // LN2 (duplicated)
    float m=0.f;
    #pragma unroll
    for (int c=0;c<NC;c++) m += xr[c];
    m *= (1.f/NC);
    float var=0.f;
    #pragma unroll
    for (int c=0;c<NC;c++){ float d=xr[c]-m; var += d*d; }
    var *= (1.f/NC);
    float inv = rsqrtf(var + EPSF);
    u64 hp[8];
    #pragma unroll
    for (int c=0;c<NC;c+=2){
        float h0 = (xr[c]-m)*inv*sg[c] + sb[c];
        float h1 = (xr[c+1]-m)*inv*sg[c+1] + sb[c+1];
        hp[c>>1] = pack2(h0, h1);
    }

    // MLP half: j in [half*32, half*32+32)
    u64 d0=0,d1=0,d2=0,d3=0,d4=0,d5=0,d6=0,d7=0;
    int j0 = half*32;
    #pragma unroll 4
    for (int jj=0;jj<32;jj++){
        int j = j0 + jj;
        const ulonglong2* wr = (const ulonglong2*)(s_w1 + j*NC);
        ulonglong2 a0 = wr[0], a1 = wr[1], a2 = wr[2], a3 = wr[3];
        u64 y2 = mul2(hp[0], a0.x);
        y2 = fma2(hp[1], a0.y, y2);
        y2 = fma2(hp[2], a1.x, y2);
        y2 = fma2(hp[3], a1.y, y2);
        y2 = fma2(hp[4], a2.x, y2);
        y2 = fma2(hp[5], a2.y, y2);
        y2 = fma2(hp[6], a3.x, y2);
        y2 = fma2(hp[7], a3.y, y2);
        float2 yf = unpack2(y2);
        float yv = fmaxf(yf.x + yf.y, 0.f);
        u64 yy = pack2(yv, yv);
        const ulonglong2* cr = (const ulonglong2*)(s_w2 + j*NC);
        ulonglong2 c0 = cr[0], c1 = cr[1], c2 = cr[2], c3 = cr[3];
        d0 = fma2(yy, c0.x, d0);
        d1 = fma2(yy, c0.y, d1);
        d2 = fma2(yy, c1.x, d2);
        d3 = fma2(yy, c1.y, d3);
        d4 = fma2(yy, c2.x, d4);
        d5 = fma2(yy, c2.y, d5);
        d6 = fma2(yy, c3.x, d6);
        d7 = fma2(yy, c3.y, d7);
    }
    // butterfly: merge the two halves' deltas (partner = lane^1, same warp)
    d0 = add2(d0, __shfl_xor_sync(0xffffffffu, d0, 1));
    d1 = add2(d1, __shfl_xor_sync(0xffffffffu, d1, 1));
    d2 = add2(d2, __shfl_xor_sync(0xffffffffu, d2, 1));
    d3 = add2(d3, __shfl_xor_sync(0xffffffffu, d3, 1));
    d4 = add2(d4, __shfl_xor_sync(0xffffffffu, d4, 1));
    d5 = add2(d5, __shfl_xor_sync(0xffffffffu, d5, 1));
    d6 = add2(d6, __shfl_xor_sync(0xffffffffu, d6, 1));
    d7 = add2(d7, __shfl_xor_sync(0xffffffffu, d7, 1));

    float2 e0=unpack2(d0), e1=unpack2(d1), e2=unpack2(d2), e3=unpack2(d3);
    float2 e4=unpack2(d4), e5=unpack2(d5), e6=unpack2(d6), e7=unpack2(d7);
    float4* xo = (float4*)g_x + (size_t)tok*4;
    if (half == 0){
        xo[0] = make_float4(xr[0]+e0.x, xr[1]+e0.y, xr[2]+e1.x, xr[3]+e1.y);
        xo[1] = make_float4(xr[4]+e2.x, xr[5]+e2.y, xr[6]+e3.x, xr[7]+e3.y);
    } else {
        xo[2] = make_float4(xr[8]+e4.x, xr[9]+e4.y, xr[10]+e5.x, xr[11]+e5.y);
        xo[3] = make_float4(xr[12]+e6.x, xr[13]+e6.y, xr[14]+e7.x, xr[15]+e7.y);
    }
}

// ---------------------------------------------------------------------------
// 4) h = LNf(x); logits = h @ tok_emb^T.
//    Block = 256 threads, 16 tokens/block; te row registered once per thread.
// ---------------------------------------------------------------------------
__global__ void __launch_bounds__(NV) head_kernel(const float* __restrict__ te,
                                                  const float* __restrict__ gf,
                                                  const float* __restrict__ bf,
                                                  float* __restrict__ out){
    int tid  = threadIdx.x;
    int warp = tid >> 5, lane = tid & 31;
    int tok0 = blockIdx.x * 16;
    __shared__ __align__(16) float hs[16][NC];

    {
        int sub = lane >> 4;           // 0 or 1
        int c   = lane & 15;
        int tok = tok0 + warp*2 + sub;
        float val = g_x[(size_t)tok*NC + c];
        float s = val;
        #pragma unroll
        for (int o=8;o>0;o>>=1) s += __shfl_xor_sync(0xffffffffu, s, o, 16);
        float m = s * (1.f/NC);
        float d = val - m;
        float vv = d*d;
        #pragma unroll
        for (int o=8;o>0;o>>=1) vv += __shfl_xor_sync(0xffffffffu, vv, o, 16);
        float inv = rsqrtf(vv*(1.f/NC) + EPSF);
        hs[warp*2+sub][c] = d*inv*gf[c] + bf[c];
    }
    __syncthreads();

    int v = tid;
    const ulonglong2* tr = (const ulonglong2*)te + v*4;
    ulonglong2 t0 = tr[0], t1 = tr[1], t2 = tr[2], t3 = tr[3];

    #pragma unroll 4
    for (int k=0;k<16;k++){
        const ulonglong2* hp = (const ulonglong2*)hs[k];
        ulonglong2 h0 = hp[0], h1 = hp[1];
        u64 s2 = mul2(h0.x, t0.x);
        s2 = fma2(h0.y, t0.y, s2);
        s2 = fma2(h1.x, t1.x, s2);
        s2 = fma2(h1.y, t1.y, s2);
        ulonglong2 h2 = hp[2], h3 = hp[3];
        s2 = fma2(h2.x, t2.x, s2);
        s2 = fma2(h2.y, t2.y, s2);
        s2 = fma2(h3.x, t3.x, s2);
        s2 = fma2(h3.y, t3.y, s2);
        float2 f = unpack2(s2);
        out[(size_t)(tok0+k)*NV + v] = f.x + f.y;
    }
}

// ---------------------------------------------------------------------------
extern "C" void kernel_launch(void* const* d_in, const int* in_sizes, int n_in,
                              void* d_out, int out_size){
    const int*   idx  = (const int*)  d_in[0];
    const float* te   = (const float*)d_in[1];
    const float* pe   = (const float*)d_in[2];
    const float* wq   = (const float*)d_in[3];
    const float* wk   = (const float*)d_in[4];
    const float* wv   = (const float*)d_in[5];
    const float* wo   = (const float*)d_in[6];
    const float* ln1g = (const float*)d_in[7];
    const float* ln1b = (const float*)d_in[8];
    const float* ln2g = (const float*)d_in[9];
    const float* ln2b = (const float*)d_in[10];
    const float* w1   = (const float*)d_in[11];
    const float* w2   = (const float*)d_in[12];
    const float* lnfg = (const float*)d_in[13];
    const float* lnfb = (const float*)d_in[14];
    float* out = (float*)d_out;

    for (int l=0; l<NL; l++){
        qkv_kernel<<<NTOK*NH/128, 128>>>(wq + l*NH*NC*NHS, wk + l*NH*NC*NHS,
                                         wv + l*NH*NC*NHS, ln1g + l*NC, ln1b + l*NC,
                                         idx, te, pe, (l==0) ? 1 : 0);
        dim3 ag(NB*NH, 4);
        attn_kernel<<<ag, 512>>>();
        post_kernel<<<NTOK*2/128, 128>>>(wo + l*NC*NC, ln2g + l*NC, ln2b + l*NC,
                                         w1 + l*4*NC*NC, w2 + l*4*NC*NC);
    }
    head_kernel<<<NTOK/16, NV>>>(te, lnfg, lnfb, out);
}

// round 7
// speedup vs baseline: 2.5146x; 2.5146x over previous
#include <cuda_runtime.h>

// MicroGPT forward, sm_103a. Fixed shapes.
#define NB  16
#define NT  2048
#define NC  16
#define NH  2
#define NHS 8
#define NL  2
#define NV  256
#define NTOK (NB*NT)
#define NQ  (NB*NH*NT)        // 65536 (bh, t) query slots
#define EPSF 1e-5f
// (1/sqrt(HS)) * log2(e): q pre-scaled so softmax uses ex2 directly
#define QSCALE 0.5100700982280911f

typedef unsigned long long u64;

// Scratch (device globals; no dynamic allocation allowed)
__device__ float g_x[NTOK*NC];
__device__ float g_q[NQ*NHS];
__device__ float g_k[NQ*NHS];
__device__ float g_v[NQ*NHS];
__device__ float g_o[NQ*NHS];
__device__ float g_pacc[2*NQ*NHS];   // split-K partial numerators
__device__ float g_pden[2*NQ];       // split-K partial denominators

__device__ __forceinline__ float ex2f(float x){
    float y; asm("ex2.approx.f32 %0, %1;" : "=f"(y) : "f"(x)); return y;
}
__device__ __forceinline__ u64 fma2(u64 a, u64 b, u64 c){
    u64 d; asm("fma.rn.f32x2 %0, %1, %2, %3;" : "=l"(d) : "l"(a), "l"(b), "l"(c)); return d;
}
__device__ __forceinline__ u64 mul2(u64 a, u64 b){
    u64 d; asm("mul.rn.f32x2 %0, %1, %2;" : "=l"(d) : "l"(a), "l"(b)); return d;
}
__device__ __forceinline__ u64 pack2(float lo, float hi){
    u64 r; asm("mov.b64 %0, {%1, %2};" : "=l"(r) : "f"(lo), "f"(hi)); return r;
}
__device__ __forceinline__ float2 unpack2(u64 v){
    float lo, hi; asm("mov.b64 {%0, %1}, %2;" : "=f"(lo), "=f"(hi) : "l"(v));
    return make_float2(lo, hi);
}

// ---------------------------------------------------------------------------
// 1) h = LN1(x); q,k,v = h @ W (q pre-scaled). Layer 0 fuses the embedding.
//    One thread per (token, head).
// ---------------------------------------------------------------------------
__global__ void __launch_bounds__(128) qkv_kernel(const float* __restrict__ wq,
                           const float* __restrict__ wk,
                           const float* __restrict__ wv,
                           const float* __restrict__ g1,
                           const float* __restrict__ b1,
                           const int*   __restrict__ idx,
                           const float* __restrict__ te,
                           const float* __restrict__ pe,
                           int fuse_embed){
    __shared__ float sq[NH*NC*NHS], sk[NH*NC*NHS], sv[NH*NC*NHS];
    __shared__ float sg[NC], sb[NC];
    int tid = threadIdx.x;
    for (int i=tid; i<NH*NC*NHS; i+=128){ sq[i]=wq[i]; sk[i]=wk[i]; sv[i]=wv[i]; }
    if (tid < NC){ sg[tid]=g1[tid]; sb[tid]=b1[tid]; }
    __syncthreads();

    int gid  = blockIdx.x*128 + tid;
    int head = gid >> 15;              // 0 or 1
    int tok  = gid & (NTOK-1);
    int b = tok >> 11;
    int t = tok & (NT-1);

    float xr[NC];
    if (fuse_embed){
        int id = idx[tok];
        const float4* t4 = (const float4*)te + id*4;
        const float4* p4 = (const float4*)pe + t*4;
        #pragma unroll
        for (int k=0;k<4;k++){
            float4 aa=t4[k], bb=p4[k];
            float4 r = make_float4(aa.x+bb.x, aa.y+bb.y, aa.z+bb.z, aa.w+bb.w);
            if (head == 0) ((float4*)g_x)[(size_t)tok*4 + k] = r;  // write once
            xr[4*k]=r.x; xr[4*k+1]=r.y; xr[4*k+2]=r.z; xr[4*k+3]=r.w;
        }
    } else {
        const float4* x4 = (const float4*)g_x + (size_t)tok*4;
        #pragma unroll
        for (int k=0;k<4;k++){
            float4 v=x4[k];
            xr[4*k]=v.x; xr[4*k+1]=v.y; xr[4*k+2]=v.z; xr[4*k+3]=v.w;
        }
    }

    float m=0.f;
    #pragma unroll
    for (int c=0;c<NC;c++) m += xr[c];
    m *= (1.f/NC);
    float var=0.f;
    #pragma unroll
    for (int c=0;c<NC;c++){ float d=xr[c]-m; var += d*d; }
    var *= (1.f/NC);
    float inv = rsqrtf(var + EPSF);
    float h[NC];
    #pragma unroll
    for (int c=0;c<NC;c++) h[c] = (xr[c]-m)*inv*sg[c] + sb[c];

    size_t obase = ((size_t)(b*NH+head)*NT + t)*NHS;
    const float* Wq = sq + head*NC*NHS;
    const float* Wk = sk + head*NC*NHS;
    const float* Wv = sv + head*NC*NHS;
    float aq[NHS], ak[NHS], av[NHS];
    #pragma unroll
    for (int s=0;s<NHS;s++){ aq[s]=0.f; ak[s]=0.f; av[s]=0.f; }
    #pragma unroll
    for (int c=0;c<NC;c++){
        float hc = h[c];
        #pragma unroll
        for (int s=0;s<NHS;s++){
            aq[s] += hc*Wq[c*NHS+s];
            ak[s] += hc*Wk[c*NHS+s];
            av[s] += hc*Wv[c*NHS+s];
        }
    }
    float4* qo = (float4*)(g_q + obase);
    float4* ko = (float4*)(g_k + obase);
    float4* vo = (float4*)(g_v + obase);
    qo[0] = make_float4(aq[0]*QSCALE, aq[1]*QSCALE, aq[2]*QSCALE, aq[3]*QSCALE);
    qo[1] = make_float4(aq[4]*QSCALE, aq[5]*QSCALE, aq[6]*QSCALE, aq[7]*QSCALE);
    ko[0] = make_float4(ak[0], ak[1], ak[2], ak[3]);
    ko[1] = make_float4(ak[4], ak[5], ak[6], ak[7]);
    vo[0] = make_float4(av[0], av[1], av[2], av[3]);
    vo[1] = make_float4(av[4], av[5], av[6], av[7]);
}

// ---------------------------------------------------------------------------
// 2) Causal attention, split-K parity + dual-query.
//    Block (bh, a, s): 128 threads; thread owns queries in tiles {a, 15-a},
//    processes key tiles kt ≡ s (mod 2), kt <= 15-a. Every thread works on
//    every staged tile (A active for kt<=a, B always). Writes unnormalized
//    partials; combine_kernel merges parities and normalizes.
//    grid = (32, 8, 2) = 512 light blocks -> self-balancing, high residency.
// ---------------------------------------------------------------------------
__global__ void __launch_bounds__(128) attn_kernel(){
    int bh   = blockIdx.x;
    int a    = blockIdx.y;              // 0..7
    int s    = blockIdx.z;              // key-tile parity
    int lane = threadIdx.x;             // 0..127
    int b = 15 - a;

    const float4* kg = (const float4*)g_k + (size_t)bh*NT*2;
    const float4* vg = (const float4*)g_v + (size_t)bh*NT*2;

    int tA = a*128 + lane;
    int tB = b*128 + lane;
    const ulonglong2* qga = (const ulonglong2*)(g_q + ((size_t)bh*NT + tA)*NHS);
    ulonglong2 qa0 = qga[0], qa1 = qga[1];
    const ulonglong2* qgb = (const ulonglong2*)(g_q + ((size_t)bh*NT + tB)*NHS);
    ulonglong2 qb0 = qgb[0], qb1 = qgb[1];

    __shared__ ulonglong2 ks[256];   // 128 keys x 32B
    __shared__ ulonglong2 vs[256];

    float denA = 0.f, denB = 0.f;
    u64 aA0=0,aA1=0,aA2=0,aA3=0;
    u64 aB0=0,aB1=0,aB2=0,aB3=0;

    for (int kt=s; kt<=b; kt+=2){
        ((float4*)ks)[lane]     = kg[kt*256 + lane];
        ((float4*)ks)[lane+128] = kg[kt*256 + lane + 128];
        ((float4*)vs)[lane]     = vg[kt*256 + lane];
        ((float4*)vs)[lane+128] = vg[kt*256 + lane + 128];
        __syncthreads();

        if (kt <= a){
            bool diag = (kt == a);
            #pragma unroll 2
            for (int j=0; j<128; j++){
                ulonglong2 k0 = ks[2*j], k1 = ks[2*j+1];
                u64 sa = mul2(qa0.x, k0.x);
                sa = fma2(qa0.y, k0.y, sa);
                sa = fma2(qa1.x, k1.x, sa);
                sa = fma2(qa1.y, k1.y, sa);
                u64 sb = mul2(qb0.x, k0.x);
                sb = fma2(qb0.y, k0.y, sb);
                sb = fma2(qb1.x, k1.x, sb);
                sb = fma2(qb1.y, k1.y, sb);
                float2 fa = unpack2(sa), fb = unpack2(sb);
                float pA = ex2f(fa.x + fa.y);
                float pB = ex2f(fb.x + fb.y);
                if (diag && j > lane) pA = 0.f;
                denA += pA; denB += pB;
                u64 ppA = pack2(pA,pA), ppB = pack2(pB,pB);
                ulonglong2 v0 = vs[2*j], v1 = vs[2*j+1];
                aA0 = fma2(ppA, v0.x, aA0);
                aA1 = fma2(ppA, v0.y, aA1);
                aA2 = fma2(ppA, v1.x, aA2);
                aA3 = fma2(ppA, v1.y, aA3);
                aB0 = fma2(ppB, v0.x, aB0);
                aB1 = fma2(ppB, v0.y, aB1);
                aB2 = fma2(ppB, v1.x, aB2);
                aB3 = fma2(ppB, v1.y, aB3);
            }
        } else {
            int jmax = (kt==b) ? (lane+1) : 128;
            #pragma unroll 4
            for (int j=0; j<jmax; j++){
                ulonglong2 k0 = ks[2*j], k1 = ks[2*j+1];
                u64 sb = mul2(qb0.x, k0.x);
                sb = fma2(qb0.y, k0.y, sb);
                sb = fma2(qb1.x, k1.x, sb);
                sb = fma2(qb1.y, k1.y, sb);
                float2 fb = unpack2(sb);
                float pB = ex2f(fb.x + fb.y);
                denB += pB;
                u64 pp = pack2(pB,pB);
                ulonglong2 v0 = vs[2*j], v1 = vs[2*j+1];
                aB0 = fma2(pp, v0.x, aB0);
                aB1 = fma2(pp, v0.y, aB1);
                aB2 = fma2(pp, v1.x, aB2);
                aB3 = fma2(pp, v1.y, aB3);
            }
        }
        __syncthreads();
    }

    // write unnormalized partials
    int pA = bh*NT + tA;
    int pB = bh*NT + tB;
    g_pden[s*NQ + pA] = denA;
    g_pden[s*NQ + pB] = denB;
    {
        float2 r0=unpack2(aA0), r1=unpack2(aA1), r2=unpack2(aA2), r3=unpack2(aA3);
        float4* op = (float4*)(g_pacc + ((size_t)s*NQ + pA)*NHS);
        op[0] = make_float4(r0.x, r0.y, r1.x, r1.y);
        op[1] = make_float4(r2.x, r2.y, r3.x, r3.y);
    }
    {
        float2 r0=unpack2(aB0), r1=unpack2(aB1), r2=unpack2(aB2), r3=unpack2(aB3);
        float4* op = (float4*)(g_pacc + ((size_t)s*NQ + pB)*NHS);
        op[0] = make_float4(r0.x, r0.y, r1.x, r1.y);
        op[1] = make_float4(r2.x, r2.y, r3.x, r3.y);
    }
}

// Combine parities + normalize: g_o = (acc0+acc1)/(den0+den1)
__global__ void __launch_bounds__(256) combine_kernel(){
    int p = blockIdx.x*256 + threadIdx.x;     // 0..NQ-1
    float den = g_pden[p] + g_pden[NQ + p];
    float inv = 1.f/den;
    const float4* a0 = (const float4*)(g_pacc + (size_t)p*NHS);
    const float4* a1 = (const float4*)(g_pacc + ((size_t)NQ + p)*NHS);
    float4 x0 = a0[0], x1 = a0[1], y0 = a1[0], y1 = a1[1];
    float4* op = (float4*)(g_o + (size_t)p*NHS);
    op[0] = make_float4((x0.x+y0.x)*inv, (x0.y+y0.y)*inv,
                        (x0.z+y0.z)*inv, (x0.w+y0.w)*inv);
    op[1] = make_float4((x1.x+y1.x)*inv, (x1.y+y1.y)*inv,
                        (x1.z+y1.z)*inv, (x1.w+y1.w)*inv);
}

// ---------------------------------------------------------------------------
// 3) x += concat(o) @ Wo^T;  h = LN2(x);  x += relu(h @ W1^T) @ W2^T
//    One thread per token; weights in smem; f32x2 throughout. (R5 version.)
// ---------------------------------------------------------------------------
__global__ void __launch_bounds__(128) post_kernel(const float* __restrict__ wo,
                            const float* __restrict__ g2,
                            const float* __restrict__ b2,
                            const float* __restrict__ w1,
                            const float* __restrict__ w2){
    __shared__ __align__(16) float s_wo[NC*NC];
    __shared__ __align__(16) float s_w1[4*NC*NC];
    __shared__ __align__(16) float s_w2[4*NC*NC];   // [j][i] = w2[i][j]
    __shared__ float sg[NC], sb[NC];
    int tid = threadIdx.x;
    for (int i=tid; i<NC*NC; i+=128) s_wo[i] = wo[i];
    for (int i=tid; i<4*NC*NC; i+=128) s_w1[i] = w1[i];
    for (int idx=tid; idx<4*NC*NC; idx+=128){
        int j = idx >> 4, i = idx & 15;
        s_w2[idx] = w2[i*(4*NC) + j];
    }
    if (tid < NC){ sg[tid]=g2[tid]; sb[tid]=b2[tid]; }
    __syncthreads();

    int tok = blockIdx.x*128 + tid;
    int b = tok >> 11;
    int t = tok & (NT-1);

    u64 o2[8];
    {
        const ulonglong2* p0 = (const ulonglong2*)(g_o + ((size_t)(b*NH+0)*NT + t)*NHS);
        const ulonglong2* p1 = (const ulonglong2*)(g_o + ((size_t)(b*NH+1)*NT + t)*NHS);
        ulonglong2 u0=p0[0], u1=p0[1], u2=p1[0], u3=p1[1];
        o2[0]=u0.x; o2[1]=u0.y; o2[2]=u1.x; o2[3]=u1.y;
        o2[4]=u2.x; o2[5]=u2.y; o2[6]=u3.x; o2[7]=u3.y;
    }

    float xr[NC];
    {
        const float4* x4 = (const float4*)g_x + (size_t)tok*4;
        #pragma unroll
        for (int k=0;k<4;k++){
            float4 v=x4[k];
            xr[4*k]=v.x; xr[4*k+1]=v.y; xr[4*k+2]=v.z; xr[4*k+3]=v.w;
        }
    }

    // Wo projection + residual (f32x2)
    #pragma unroll
    for (int i=0;i<NC;i++){
        const ulonglong2* wr = (const ulonglong2*)(s_wo + i*NC);
        ulonglong2 w0 = wr[0], w1r = wr[1];
        u64 s2 = mul2(o2[0], w0.x);
        s2 = fma2(o2[1], w0.y, s2);
        s2 = fma2(o2[2], w1r.x, s2);
        s2 = fma2(o2[3], w1r.y, s2);
        ulonglong2 w2r = wr[2], w3r = wr[3];
        s2 = fma2(o2[4], w2r.x, s2);
        s2 = fma2(o2[5], w2r.y, s2);
        s2 = fma2(o2[6], w3r.x, s2);
        s2 = fma2(o2[7], w3r.y, s2);
        float2 f = unpack2(s2);
        xr[i] += f.x + f.y;
    }

    // LN2
    float m=0.f;
    #pragma unroll
    for (int c=0;c<NC;c++) m += xr[c];
    m *= (1.f/NC);
    float var=0.f;
    #pragma unroll
    for (int c=0;c<NC;c++){ float d=xr[c]-m; var += d*d; }
    var *= (1.f/NC);
    float inv = rsqrtf(var + EPSF);
    u64 hp[8];
    #pragma unroll
    for (int c=0;c<NC;c+=2){
        float h0 = (xr[c]-m)*inv*sg[c] + sb[c];
        float h1 = (xr[c+1]-m)*inv*sg[c+1] + sb[c+1];
        hp[c>>1] = pack2(h0, h1);
    }

    // MLP (f32x2)
    u64 d0=0,d1=0,d2=0,d3=0,d4=0,d5=0,d6=0,d7=0;
    #pragma unroll 4
    for (int j=0;j<4*NC;j++){
        const ulonglong2* wr = (const ulonglong2*)(s_w1 + j*NC);
        ulonglong2 a0 = wr[0], a1 = wr[1], a2 = wr[2], a3 = wr[3];
        u64 y2 = mul2(hp[0], a0.x);
        y2 = fma2(hp[1], a0.y, y2);
        y2 = fma2(hp[2], a1.x, y2);
        y2 = fma2(hp[3], a1.y, y2);
        y2 = fma2(hp[4], a2.x, y2);
        y2 = fma2(hp[5], a2.y, y2);
        y2 = fma2(hp[6], a3.x, y2);
        y2 = fma2(hp[7], a3.y, y2);
        float2 yf = unpack2(y2);
        float yv = fmaxf(yf.x + yf.y, 0.f);
        u64 yy = pack2(yv, yv);
        const ulonglong2* cr = (const ulonglong2*)(s_w2 + j*NC);
        ulonglong2 c0 = cr[0], c1 = cr[1], c2 = cr[2], c3 = cr[3];
        d0 = fma2(yy, c0.x, d0);
        d1 = fma2(yy, c0.y, d1);
        d2 = fma2(yy, c1.x, d2);
        d3 = fma2(yy, c1.y, d3);
        d4 = fma2(yy, c2.x, d4);
        d5 = fma2(yy, c2.y, d5);
        d6 = fma2(yy, c3.x, d6);
        d7 = fma2(yy, c3.y, d7);
    }
    float2 e0=unpack2(d0), e1=unpack2(d1), e2=unpack2(d2), e3=unpack2(d3);
    float2 e4=unpack2(d4), e5=unpack2(d5), e6=unpack2(d6), e7=unpack2(d7);
    xr[0]+=e0.x; xr[1]+=e0.y; xr[2]+=e1.x; xr[3]+=e1.y;
    xr[4]+=e2.x; xr[5]+=e2.y; xr[6]+=e3.x; xr[7]+=e3.y;
    xr[8]+=e4.x; xr[9]+=e4.y; xr[10]+=e5.x; xr[11]+=e5.y;
    xr[12]+=e6.x; xr[13]+=e6.y; xr[14]+=e7.x; xr[15]+=e7.y;

    float4* xo = (float4*)g_x + (size_t)tok*4;
    #pragma unroll
    for (int k=0;k<4;k++)
        xo[k] = make_float4(xr[4*k], xr[4*k+1], xr[4*k+2], xr[4*k+3]);
}

// ---------------------------------------------------------------------------
// 4) h = LNf(x); logits = h @ tok_emb^T.
//    Block = 256 threads, 16 tokens/block; te row registered once per thread.
// ---------------------------------------------------------------------------
__global__ void __launch_bounds__(NV) head_kernel(const float* __restrict__ te,
                                                  const float* __restrict__ gf,
                                                  const float* __restrict__ bf,
                                                  float* __restrict__ out){
    int tid  = threadIdx.x;
    int warp = tid >> 5, lane = tid & 31;
    int tok0 = blockIdx.x * 16;
    __shared__ __align__(16) float hs[16][NC];

    {
        int sub = lane >> 4;           // 0 or 1
        int c   = lane & 15;
        int tok = tok0 + warp*2 + sub;
        float val = g_x[(size_t)tok*NC + c];
        float s = val;
        #pragma unroll
        for (int o=8;o>0;o>>=1) s += __shfl_xor_sync(0xffffffffu, s, o, 16);
        float m = s * (1.f/NC);
        float d = val - m;
        float vv = d*d;
        #pragma unroll
        for (int o=8;o>0;o>>=1) vv += __shfl_xor_sync(0xffffffffu, vv, o, 16);
        float inv = rsqrtf(vv*(1.f/NC) + EPSF);
        hs[warp*2+sub][c] = d*inv*gf[c] + bf[c];
    }
    __syncthreads();

    int v = tid;
    const ulonglong2* tr = (const ulonglong2*)te + v*4;
    ulonglong2 t0 = tr[0], t1 = tr[1], t2 = tr[2], t3 = tr[3];

    #pragma unroll 4
    for (int k=0;k<16;k++){
        const ulonglong2* hp = (const ulonglong2*)hs[k];
        ulonglong2 h0 = hp[0], h1 = hp[1];
        u64 s2 = mul2(h0.x, t0.x);
        s2 = fma2(h0.y, t0.y, s2);
        s2 = fma2(h1.x, t1.x, s2);
        s2 = fma2(h1.y, t1.y, s2);
        ulonglong2 h2 = hp[2], h3 = hp[3];
        s2 = fma2(h2.x, t2.x, s2);
        s2 = fma2(h2.y, t2.y, s2);
        s2 = fma2(h3.x, t3.x, s2);
        s2 = fma2(h3.y, t3.y, s2);
        float2 f = unpack2(s2);
        out[(size_t)(tok0+k)*NV + v] = f.x + f.y;
    }
}

// ---------------------------------------------------------------------------
extern "C" void kernel_launch(void* const* d_in, const int* in_sizes, int n_in,
                              void* d_out, int out_size){
    const int*   idx  = (const int*)  d_in[0];
    const float* te   = (const float*)d_in[1];
    const float* pe   = (const float*)d_in[2];
    const float* wq   = (const float*)d_in[3];
    const float* wk   = (const float*)d_in[4];
    const float* wv   = (const float*)d_in[5];
    const float* wo   = (const float*)d_in[6];
    const float* ln1g = (const float*)d_in[7];
    const float* ln1b = (const float*)d_in[8];
    const float* ln2g = (const float*)d_in[9];
    const float* ln2b = (const float*)d_in[10];
    const float* w1   = (const float*)d_in[11];
    const float* w2   = (const float*)d_in[12];
    const float* lnfg = (const float*)d_in[13];
    const float* lnfb = (const float*)d_in[14];
    float* out = (float*)d_out;

    for (int l=0; l<NL; l++){
        qkv_kernel<<<NTOK*NH/128, 128>>>(wq + l*NH*NC*NHS, wk + l*NH*NC*NHS,
                                         wv + l*NH*NC*NHS, ln1g + l*NC, ln1b + l*NC,
                                         idx, te, pe, (l==0) ? 1 : 0);
        dim3 ag(NB*NH, 8, 2);
        attn_kernel<<<ag, 128>>>();
        combine_kernel<<<NQ/256, 256>>>();
        post_kernel<<<NTOK/128, 128>>>(wo + l*NC*NC, ln2g + l*NC, ln2b + l*NC,
                                       w1 + l*4*NC*NC, w2 + l*4*NC*NC);
    }
    head_kernel<<<NTOK/16, NV>>>(te, lnfg, lnfb, out);
}

// round 9
// speedup vs baseline: 2.5897x; 1.0298x over previous
#include <cuda_runtime.h>

// MicroGPT forward, sm_103a. Fixed shapes.
#define NB  16
#define NT  2048
#define NC  16
#define NH  2
#define NHS 8
#define NL  2
#define NV  256
#define NTOK (NB*NT)
#define NQ  (NB*NH*NT)        // 65536 (bh, t) query slots
#define NSPLIT 4
#define EPSF 1e-5f
// (1/sqrt(HS)) * log2(e): q pre-scaled so softmax uses ex2 directly
#define QSCALE 0.5100700982280911f

typedef unsigned long long u64;

// Scratch (device globals; no dynamic allocation allowed)
__device__ float g_x[NTOK*NC];
__device__ float g_q[NQ*NHS];
__device__ float g_k[NQ*NHS];
__device__ float g_v[NQ*NHS];
__device__ float g_o[NQ*NHS];
__device__ float g_pacc[NSPLIT*NQ*NHS];   // split-K partial numerators
__device__ float g_pden[NSPLIT*NQ];       // split-K partial denominators

__device__ __forceinline__ float ex2f(float x){
    float y; asm("ex2.approx.f32 %0, %1;" : "=f"(y) : "f"(x)); return y;
}
__device__ __forceinline__ u64 fma2(u64 a, u64 b, u64 c){
    u64 d; asm("fma.rn.f32x2 %0, %1, %2, %3;" : "=l"(d) : "l"(a), "l"(b), "l"(c)); return d;
}
__device__ __forceinline__ u64 mul2(u64 a, u64 b){
    u64 d; asm("mul.rn.f32x2 %0, %1, %2;" : "=l"(d) : "l"(a), "l"(b)); return d;
}
__device__ __forceinline__ u64 pack2(float lo, float hi){
    u64 r; asm("mov.b64 %0, {%1, %2};" : "=l"(r) : "f"(lo), "f"(hi)); return r;
}
__device__ __forceinline__ float2 unpack2(u64 v){
    float lo, hi; asm("mov.b64 {%0, %1}, %2;" : "=f"(lo), "=f"(hi) : "l"(v));
    return make_float2(lo, hi);
}

// ---------------------------------------------------------------------------
// 1) h = LN1(x); one of {q,k,v} = h @ W (q pre-scaled). Layer 0 fuses embed.
//    One thread per (type, head, token): type = gid>>16 (q/k/v).
// ---------------------------------------------------------------------------
__global__ void __launch_bounds__(128) qkv_kernel(const float* __restrict__ wq,
                           const float* __restrict__ wk,
                           const float* __restrict__ wv,
                           const float* __restrict__ g1,
                           const float* __restrict__ b1,
                           const int*   __restrict__ idx,
                           const float* __restrict__ te,
                           const float* __restrict__ pe,
                           int fuse_embed){
    __shared__ float sq[NH*NC*NHS], sk[NH*NC*NHS], sv[NH*NC*NHS];
    __shared__ float sg[NC], sb[NC];
    int tid = threadIdx.x;
    for (int i=tid; i<NH*NC*NHS; i+=128){ sq[i]=wq[i]; sk[i]=wk[i]; sv[i]=wv[i]; }
    if (tid < NC){ sg[tid]=g1[tid]; sb[tid]=b1[tid]; }
    __syncthreads();

    int gid  = blockIdx.x*128 + tid;
    int type = gid >> 16;              // 0=q, 1=k, 2=v (uniform per block)
    int rem  = gid & 0xFFFF;
    int head = rem >> 15;              // 0 or 1
    int tok  = rem & (NTOK-1);
    int b = tok >> 11;
    int t = tok & (NT-1);

    float xr[NC];
    if (fuse_embed){
        int id = idx[tok];
        const float4* t4 = (const float4*)te + id*4;
        const float4* p4 = (const float4*)pe + t*4;
        bool wr = (type==0) && (head==0);
        #pragma unroll
        for (int k=0;k<4;k++){
            float4 aa=t4[k], bb=p4[k];
            float4 r = make_float4(aa.x+bb.x, aa.y+bb.y, aa.z+bb.z, aa.w+bb.w);
            if (wr) ((float4*)g_x)[(size_t)tok*4 + k] = r;  // write once
            xr[4*k]=r.x; xr[4*k+1]=r.y; xr[4*k+2]=r.z; xr[4*k+3]=r.w;
        }
    } else {
        const float4* x4 = (const float4*)g_x + (size_t)tok*4;
        #pragma unroll
        for (int k=0;k<4;k++){
            float4 v=x4[k];
            xr[4*k]=v.x; xr[4*k+1]=v.y; xr[4*k+2]=v.z; xr[4*k+3]=v.w;
        }
    }

    float m=0.f;
    #pragma unroll
    for (int c=0;c<NC;c++) m += xr[c];
    m *= (1.f/NC);
    float var=0.f;
    #pragma unroll
    for (int c=0;c<NC;c++){ float d=xr[c]-m; var += d*d; }
    var *= (1.f/NC);
    float inv = rsqrtf(var + EPSF);
    float h[NC];
    #pragma unroll
    for (int c=0;c<NC;c++) h[c] = (xr[c]-m)*inv*sg[c] + sb[c];

    const float* W = (type==0 ? sq : (type==1 ? sk : sv)) + head*NC*NHS;
    float acc[NHS];
    #pragma unroll
    for (int s=0;s<NHS;s++) acc[s]=0.f;
    #pragma unroll
    for (int c=0;c<NC;c++){
        float hc = h[c];
        #pragma unroll
        for (int s=0;s<NHS;s++) acc[s] += hc*W[c*NHS+s];
    }
    float scale = (type==0) ? QSCALE : 1.f;
    size_t obase = ((size_t)(b*NH+head)*NT + t)*NHS;
    float* dst = (type==0 ? g_q : (type==1 ? g_k : g_v)) + obase;
    ((float4*)dst)[0] = make_float4(acc[0]*scale, acc[1]*scale, acc[2]*scale, acc[3]*scale);
    ((float4*)dst)[1] = make_float4(acc[4]*scale, acc[5]*scale, acc[6]*scale, acc[7]*scale);
}

// ---------------------------------------------------------------------------
// 2) Causal attention, split-K mod-4 + dual-query.
//    Block (bh, a, s): 128 threads; thread owns queries in tiles {a, 15-a},
//    processes key tiles kt ≡ s (mod 4), kt <= 15-a. Unnormalized partials.
//    grid = (32, 8, 4) = 1024 blocks -> ~7 blocks/SM, ~7 warps/SMSP.
// ---------------------------------------------------------------------------
__global__ void __launch_bounds__(128) attn_kernel(){
    int bh   = blockIdx.x;
    int a    = blockIdx.y;              // 0..7
    int s    = blockIdx.z;              // key-tile residue mod 4
    int lane = threadIdx.x;             // 0..127
    int b = 15 - a;

    const float4* kg = (const float4*)g_k + (size_t)bh*NT*2;
    const float4* vg = (const float4*)g_v + (size_t)bh*NT*2;

    int tA = a*128 + lane;
    int tB = b*128 + lane;
    const ulonglong2* qga = (const ulonglong2*)(g_q + ((size_t)bh*NT + tA)*NHS);
    ulonglong2 qa0 = qga[0], qa1 = qga[1];
    const ulonglong2* qgb = (const ulonglong2*)(g_q + ((size_t)bh*NT + tB)*NHS);
    ulonglong2 qb0 = qgb[0], qb1 = qgb[1];

    __shared__ ulonglong2 ks[256];   // 128 keys x 32B
    __shared__ ulonglong2 vs[256];

    float denA = 0.f, denB = 0.f;
    u64 aA0=0,aA1=0,aA2=0,aA3=0;
    u64 aB0=0,aB1=0,aB2=0,aB3=0;

    for (int kt=s; kt<=b; kt+=NSPLIT){
        ((float4*)ks)[lane]     = kg[kt*256 + lane];
        ((float4*)ks)[lane+128] = kg[kt*256 + lane + 128];
        ((float4*)vs)[lane]     = vg[kt*256 + lane];
        ((float4*)vs)[lane+128] = vg[kt*256 + lane + 128];
        __syncthreads();

        if (kt <= a){
            bool diag = (kt == a);
            #pragma unroll 2
            for (int j=0; j<128; j++){
                ulonglong2 k0 = ks[2*j], k1 = ks[2*j+1];
                u64 sa = mul2(qa0.x, k0.x);
                sa = fma2(qa0.y, k0.y, sa);
                sa = fma2(qa1.x, k1.x, sa);
                sa = fma2(qa1.y, k1.y, sa);
                u64 sb = mul2(qb0.x, k0.x);
                sb = fma2(qb0.y, k0.y, sb);
                sb = fma2(qb1.x, k1.x, sb);
                sb = fma2(qb1.y, k1.y, sb);
                float2 fa = unpack2(sa), fb = unpack2(sb);
                float pA = ex2f(fa.x + fa.y);
                float pB = ex2f(fb.x + fb.y);
                if (diag && j > lane) pA = 0.f;
                denA += pA; denB += pB;
                u64 ppA = pack2(pA,pA), ppB = pack2(pB,pB);
                ulonglong2 v0 = vs[2*j], v1 = vs[2*j+1];
                aA0 = fma2(ppA, v0.x, aA0);
                aA1 = fma2(ppA, v0.y, aA1);
                aA2 = fma2(ppA, v1.x, aA2);
                aA3 = fma2(ppA, v1.y, aA3);
                aB0 = fma2(ppB, v0.x, aB0);
                aB1 = fma2(ppB, v0.y, aB1);
                aB2 = fma2(ppB, v1.x, aB2);
                aB3 = fma2(ppB, v1.y, aB3);
            }
        } else {
            int jmax = (kt==b) ? (lane+1) : 128;
            #pragma unroll 4
            for (int j=0; j<jmax; j++){
                ulonglong2 k0 = ks[2*j], k1 = ks[2*j+1];
                u64 sb = mul2(qb0.x, k0.x);
                sb = fma2(qb0.y, k0.y, sb);
                sb = fma2(qb1.x, k1.x, sb);
                sb = fma2(qb1.y, k1.y, sb);
                float2 fb = unpack2(sb);
                float pB = ex2f(fb.x + fb.y);
                denB += pB;
                u64 pp = pack2(pB,pB);
                ulonglong2 v0 = vs[2*j], v1 = vs[2*j+1];
                aB0 = fma2(pp, v0.x, aB0);
                aB1 = fma2(pp, v0.y, aB1);
                aB2 = fma2(pp, v1.x, aB2);
                aB3 = fma2(pp, v1.y, aB3);
            }
        }
        __syncthreads();
    }

    // write unnormalized partials
    int pA = bh*NT + tA;
    int pB = bh*NT + tB;
    g_pden[s*NQ + pA] = denA;
    g_pden[s*NQ + pB] = denB;
    {
        float2 r0=unpack2(aA0), r1=unpack2(aA1), r2=unpack2(aA2), r3=unpack2(aA3);
        float4* op = (float4*)(g_pacc + ((size_t)s*NQ + pA)*NHS);
        op[0] = make_float4(r0.x, r0.y, r1.x, r1.y);
        op[1] = make_float4(r2.x, r2.y, r3.x, r3.y);
    }
    {
        float2 r0=unpack2(aB0), r1=unpack2(aB1), r2=unpack2(aB2), r3=unpack2(aB3);
        float4* op = (float4*)(g_pacc + ((size_t)s*NQ + pB)*NHS);
        op[0] = make_float4(r0.x, r0.y, r1.x, r1.y);
        op[1] = make_float4(r2.x, r2.y, r3.x, r3.y);
    }
}

// Combine splits + normalize: g_o = (Σ acc_s)/(Σ den_s)
__global__ void __launch_bounds__(256) combine_kernel(){
    int p = blockIdx.x*256 + threadIdx.x;     // 0..NQ-1
    float den = 0.f;
    #pragma unroll
    for (int s=0;s<NSPLIT;s++) den += g_pden[s*NQ + p];
    float inv = 1.f/den;
    float4 r0 = make_float4(0,0,0,0), r1 = make_float4(0,0,0,0);
    #pragma unroll
    for (int s=0;s<NSPLIT;s++){
        const float4* ap = (const float4*)(g_pacc + ((size_t)s*NQ + p)*NHS);
        float4 x0 = ap[0], x1 = ap[1];
        r0.x+=x0.x; r0.y+=x0.y; r0.z+=x0.z; r0.w+=x0.w;
        r1.x+=x1.x; r1.y+=x1.y; r1.z+=x1.z; r1.w+=x1.w;
    }
    float4* op = (float4*)(g_o + (size_t)p*NHS);
    op[0] = make_float4(r0.x*inv, r0.y*inv, r0.z*inv, r0.w*inv);
    op[1] = make_float4(r1.x*inv, r1.y*inv, r1.z*inv, r1.w*inv);
}

// ---------------------------------------------------------------------------
// 3) x += concat(o) @ Wo^T;  h = LN2(x);  x += relu(h @ W1^T) @ W2^T
//    Two threads per token: each does 32 of the 64 hidden units, lane^1
//    butterfly merges deltas, stores split between the pair.
// ---------------------------------------------------------------------------
__global__ void __launch_bounds__(128) post_kernel(const float* __restrict__ wo,
                            const float* __restrict__ g2,
                            const float* __restrict__ b2,
                            const float* __restrict__ w1,
                            const float* __restrict__ w2){
    __shared__ __align__(16) float s_wo[NC*NC];
    __shared__ __align__(16) float s_w1[4*NC*NC];
    __shared__ __align__(16) float s_w2[4*NC*NC];   // [j][i] = w2[i][j]
    __shared__ float sg[NC], sb[NC];
    int tid = threadIdx.x;
    for (int i=tid; i<NC*NC; i+=128) s_wo[i] = wo[i];
    for (int i=tid; i<4*NC*NC; i+=128) s_w1[i] = w1[i];
    for (int idx=tid; idx<4*NC*NC; idx+=128){
        int j = idx >> 4, i = idx & 15;
        s_w2[idx] = w2[i*(4*NC) + j];
    }
    if (tid < NC){ sg[tid]=g2[tid]; sb[tid]=b2[tid]; }
    __syncthreads();

    int gid  = blockIdx.x*128 + tid;
    int half = gid & 1;
    int tok  = gid >> 1;
    int b = tok >> 11;
    int t = tok & (NT-1);

    u64 o2[8];
    {
        const ulonglong2* p0 = (const ulonglong2*)(g_o + ((size_t)(b*NH+0)*NT + t)*NHS);
        const ulonglong2* p1 = (const ulonglong2*)(g_o + ((size_t)(b*NH+1)*NT + t)*NHS);
        ulonglong2 u0=p0[0], u1=p0[1], u2=p1[0], u3=p1[1];
        o2[0]=u0.x; o2[1]=u0.y; o2[2]=u1.x; o2[3]=u1.y;
        o2[4]=u2.x; o2[5]=u2.y; o2[6]=u3.x; o2[7]=u3.y;
    }

    float xr[NC];
    {
        const float4* x4 = (const float4*)g_x + (size_t)tok*4;
        #pragma unroll
        for (int k=0;k<4;k++){
            float4 v=x4[k];
            xr[4*k]=v.x; xr[4*k+1]=v.y; xr[4*k+2]=v.z; xr[4*k+3]=v.w;
        }
    }

    // Wo projection + residual (f32x2) — duplicated across the pair
    #pragma unroll
    for (int i=0;i<NC;i++){
        const ulonglong2* wr = (const ulonglong2*)(s_wo + i*NC);
        ulonglong2 w0 = wr[0], w1r = wr[1];
        u64 s2 = mul2(o2[0], w0.x);
        s2 = fma2(o2[1], w0.y, s2);
        s2 = fma2(o2[2], w1r.x, s2);
        s2 = fma2(o2[3], w1r.y, s2);
        ulonglong2 w2r = wr[2], w3r = wr[3];
        s2 = fma2(o2[4], w2r.x, s2);
        s2 = fma2(o2[5], w2r.y, s2);
        s2 = fma2(o2[6], w3r.x, s2);
        s2 = fma2(o2[7], w3r.y, s2);
        float2 f = unpack2(s2);
        xr[i] += f.x + f.y;
    }

    // LN2 (duplicated)
    float m=0.f;
    #pragma unroll
    for (int c=0;c<NC;c++) m += xr[c];
    m *= (1.f/NC);
    float var=0.f;
    #pragma unroll
    for (int c=0;c<NC;c++){ float d=xr[c]-m; var += d*d; }
    var *= (1.f/NC);
    float inv = rsqrtf(var + EPSF);
    u64 hp[8];
    #pragma unroll
    for (int c=0;c<NC;c+=2){
        float h0 = (xr[c]-m)*inv*sg[c] + sb[c];
        float h1 = (xr[c+1]-m)*inv*sg[c+1] + sb[c+1];
        hp[c>>1] = pack2(h0, h1);
    }

    // MLP half: j in [half*32, half*32+32)
    u64 d0=0,d1=0,d2=0,d3=0,d4=0,d5=0,d6=0,d7=0;
    int j0 = half*32;
    #pragma unroll 4
    for (int jj=0;jj<32;jj++){
        int j = j0 + jj;
        const ulonglong2* wr = (const ulonglong2*)(s_w1 + j*NC);
        ulonglong2 a0 = wr[0], a1 = wr[1], a2 = wr[2], a3 = wr[3];
        u64 y2 = mul2(hp[0], a0.x);
        y2 = fma2(hp[1], a0.y, y2);
        y2 = fma2(hp[2], a1.x, y2);
        y2 = fma2(hp[3], a1.y, y2);
        y2 = fma2(hp[4], a2.x, y2);
        y2 = fma2(hp[5], a2.y, y2);
        y2 = fma2(hp[6], a3.x, y2);
        y2 = fma2(hp[7], a3.y, y2);
        float2 yf = unpack2(y2);
        float yv = fmaxf(yf.x + yf.y, 0.f);
        u64 yy = pack2(yv, yv);
        const ulonglong2* cr = (const ulonglong2*)(s_w2 + j*NC);
        ulonglong2 c0 = cr[0], c1 = cr[1], c2 = cr[2], c3 = cr[3];
        d0 = fma2(yy, c0.x, d0);
        d1 = fma2(yy, c0.y, d1);
        d2 = fma2(yy, c1.x, d2);
        d3 = fma2(yy, c1.y, d3);
        d4 = fma2(yy, c2.x, d4);
        d5 = fma2(yy, c2.y, d5);
        d6 = fma2(yy, c3.x, d6);
        d7 = fma2(yy, c3.y, d7);
    }
    // butterfly: merge the two halves' deltas (partner = lane^1, same warp)
    {
        u64 t0;
        t0 = __shfl_xor_sync(0xffffffffu, d0, 1); { float2 a=unpack2(d0), c=unpack2(t0); d0 = pack2(a.x+c.x, a.y+c.y); }
        t0 = __shfl_xor_sync(0xffffffffu, d1, 1); { float2 a=unpack2(d1), c=unpack2(t0); d1 = pack2(a.x+c.x, a.y+c.y); }
        t0 = __shfl_xor_sync(0xffffffffu, d2, 1); { float2 a=unpack2(d2), c=unpack2(t0); d2 = pack2(a.x+c.x, a.y+c.y); }
        t0 = __shfl_xor_sync(0xffffffffu, d3, 1); { float2 a=unpack2(d3), c=unpack2(t0); d3 = pack2(a.x+c.x, a.y+c.y); }
        t0 = __shfl_xor_sync(0xffffffffu, d4, 1); { float2 a=unpack2(d4), c=unpack2(t0); d4 = pack2(a.x+c.x, a.y+c.y); }
        t0 = __shfl_xor_sync(0xffffffffu, d5, 1); { float2 a=unpack2(d5), c=unpack2(t0); d5 = pack2(a.x+c.x, a.y+c.y); }
        t0 = __shfl_xor_sync(0xffffffffu, d6, 1); { float2 a=unpack2(d6), c=unpack2(t0); d6 = pack2(a.x+c.x, a.y+c.y); }
        t0 = __shfl_xor_sync(0xffffffffu, d7, 1); { float2 a=unpack2(d7), c=unpack2(t0); d7 = pack2(a.x+c.x, a.y+c.y); }
    }

    float2 e0=unpack2(d0), e1=unpack2(d1), e2=unpack2(d2), e3=unpack2(d3);
    float2 e4=unpack2(d4), e5=unpack2(d5), e6=unpack2(d6), e7=unpack2(d7);
    float4* xo = (float4*)g_x + (size_t)tok*4;
    if (half == 0){
        xo[0] = make_float4(xr[0]+e0.x, xr[1]+e0.y, xr[2]+e1.x, xr[3]+e1.y);
        xo[1] = make_float4(xr[4]+e2.x, xr[5]+e2.y, xr[6]+e3.x, xr[7]+e3.y);
    } else {
        xo[2] = make_float4(xr[8]+e4.x, xr[9]+e4.y, xr[10]+e5.x, xr[11]+e5.y);
        xo[3] = make_float4(xr[12]+e6.x, xr[13]+e6.y, xr[14]+e7.x, xr[15]+e7.y);
    }
}

// ---------------------------------------------------------------------------
// 4) h = LNf(x); logits = h @ tok_emb^T.
//    Block = 256 threads, 16 tokens/block; te row registered once per thread.
// ---------------------------------------------------------------------------
__global__ void __launch_bounds__(NV) head_kernel(const float* __restrict__ te,
                                                  const float* __restrict__ gf,
                                                  const float* __restrict__ bf,
                                                  float* __restrict__ out){
    int tid  = threadIdx.x;
    int warp = tid >> 5, lane = tid & 31;
    int tok0 = blockIdx.x * 16;
    __shared__ __align__(16) float hs[16][NC];

    {
        int sub = lane >> 4;           // 0 or 1
        int c   = lane & 15;
        int tok = tok0 + warp*2 + sub;
        float val = g_x[(size_t)tok*NC + c];
        float s = val;
        #pragma unroll
        for (int o=8;o>0;o>>=1) s += __shfl_xor_sync(0xffffffffu, s, o, 16);
        float m = s * (1.f/NC);
        float d = val - m;
        float vv = d*d;
        #pragma unroll
        for (int o=8;o>0;o>>=1) vv += __shfl_xor_sync(0xffffffffu, vv, o, 16);
        float inv = rsqrtf(vv*(1.f/NC) + EPSF);
        hs[warp*2+sub][c] = d*inv*gf[c] + bf[c];
    }
    __syncthreads();

    int v = tid;
    const ulonglong2* tr = (const ulonglong2*)te + v*4;
    ulonglong2 t0 = tr[0], t1 = tr[1], t2 = tr[2], t3 = tr[3];

    #pragma unroll 4
    for (int k=0;k<16;k++){
        const ulonglong2* hp = (const ulonglong2*)hs[k];
        ulonglong2 h0 = hp[0], h1 = hp[1];
        u64 s2 = mul2(h0.x, t0.x);
        s2 = fma2(h0.y, t0.y, s2);
        s2 = fma2(h1.x, t1.x, s2);
        s2 = fma2(h1.y, t1.y, s2);
        ulonglong2 h2 = hp[2], h3 = hp[3];
        s2 = fma2(h2.x, t2.x, s2);
        s2 = fma2(h2.y, t2.y, s2);
        s2 = fma2(h3.x, t3.x, s2);
        s2 = fma2(h3.y, t3.y, s2);
        float2 f = unpack2(s2);
        out[(size_t)(tok0+k)*NV + v] = f.x + f.y;
    }
}

// ---------------------------------------------------------------------------
extern "C" void kernel_launch(void* const* d_in, const int* in_sizes, int n_in,
                              void* d_out, int out_size){
    const int*   idx  = (const int*)  d_in[0];
    const float* te   = (const float*)d_in[1];
    const float* pe   = (const float*)d_in[2];
    const float* wq   = (const float*)d_in[3];
    const float* wk   = (const float*)d_in[4];
    const float* wv   = (const float*)d_in[5];
    const float* wo   = (const float*)d_in[6];
    const float* ln1g = (const float*)d_in[7];
    const float* ln1b = (const float*)d_in[8];
    const float* ln2g = (const float*)d_in[9];
    const float* ln2b = (const float*)d_in[10];
    const float* w1   = (const float*)d_in[11];
    const float* w2   = (const float*)d_in[12];
    const float* lnfg = (const float*)d_in[13];
    const float* lnfb = (const float*)d_in[14];
    float* out = (float*)d_out;

    for (int l=0; l<NL; l++){
        qkv_kernel<<<NTOK*NH*3/128, 128>>>(wq + l*NH*NC*NHS, wk + l*NH*NC*NHS,
                                           wv + l*NH*NC*NHS, ln1g + l*NC, ln1b + l*NC,
                                           idx, te, pe, (l==0) ? 1 : 0);
        dim3 ag(NB*NH, 8, NSPLIT);
        attn_kernel<<<ag, 128>>>();
        combine_kernel<<<NQ/256, 256>>>();
        post_kernel<<<NTOK*2/128, 128>>>(wo + l*NC*NC, ln2g + l*NC, ln2b + l*NC,
                                         w1 + l*4*NC*NC, w2 + l*4*NC*NC);
    }
    head_kernel<<<NTOK/16, NV>>>(te, lnfg, lnfb, out);
}

// round 13
// speedup vs baseline: 2.8086x; 1.0845x over previous
#include <cuda_runtime.h>

// MicroGPT forward, sm_103a. Fixed shapes.
#define NB  16
#define NT  2048
#define NC  16
#define NH  2
#define NHS 8
#define NL  2
#define NV  256
#define NTOK (NB*NT)
#define NQ  (NB*NH*NT)        // 65536 (bh, t) query slots
#define NSPLIT 4
#define EPSF 1e-5f
// (1/sqrt(HS)) * log2(e): q pre-scaled so softmax uses ex2 directly
#define QSCALE 0.5100700982280911f

typedef unsigned long long u64;

// Scratch (device globals; no dynamic allocation allowed)
__device__ float g_x[NTOK*NC];
__device__ float g_q[NQ*NHS];
__device__ float g_k[NQ*NHS];
__device__ float g_v[NQ*NHS];
__device__ float g_pacc[NSPLIT*NQ*NHS];   // split-K partial numerators
__device__ float g_pden[NSPLIT*NQ];       // split-K partial denominators

__device__ __forceinline__ float ex2f(float x){
    float y; asm("ex2.approx.f32 %0, %1;" : "=f"(y) : "f"(x)); return y;
}
__device__ __forceinline__ u64 fma2(u64 a, u64 b, u64 c){
    u64 d; asm("fma.rn.f32x2 %0, %1, %2, %3;" : "=l"(d) : "l"(a), "l"(b), "l"(c)); return d;
}
__device__ __forceinline__ u64 mul2(u64 a, u64 b){
    u64 d; asm("mul.rn.f32x2 %0, %1, %2;" : "=l"(d) : "l"(a), "l"(b)); return d;
}
__device__ __forceinline__ u64 add2(u64 a, u64 b){
    u64 d; asm("add.rn.f32x2 %0, %1, %2;" : "=l"(d) : "l"(a), "l"(b)); return d;
}
__device__ __forceinline__ u64 pack2(float lo, float hi){
    u64 r; asm("mov.b64 %0, {%1, %2};" : "=l"(r) : "f"(lo), "f"(hi)); return r;
}
__device__ __forceinline__ float2 unpack2(u64 v){
    float lo, hi; asm("mov.b64 {%0, %1}, %2;" : "=f"(lo), "=f"(hi) : "l"(v));
    return make_float2(lo, hi);
}

// ---------------------------------------------------------------------------
// 1) h = LN1(x); one of {q,k,v} = h @ W (q pre-scaled). Layer 0 fuses embed.
//    One thread per (type, head, token): type = gid>>16 (q/k/v).
// ---------------------------------------------------------------------------
__global__ void __launch_bounds__(128) qkv_kernel(const float* __restrict__ wq,
                           const float* __restrict__ wk,
                           const float* __restrict__ wv,
                           const float* __restrict__ g1,
                           const float* __restrict__ b1,
                           const int*   __restrict__ idx,
                           const float* __restrict__ te,
                           const float* __restrict__ pe,
                           int fuse_embed){
    __shared__ float sq[NH*NC*NHS], sk[NH*NC*NHS], sv[NH*NC*NHS];
    __shared__ float sg[NC], sb[NC];
    int tid = threadIdx.x;
    for (int i=tid; i<NH*NC*NHS; i+=128){ sq[i]=wq[i]; sk[i]=wk[i]; sv[i]=wv[i]; }
    if (tid < NC){ sg[tid]=g1[tid]; sb[tid]=b1[tid]; }
    __syncthreads();

    int gid  = blockIdx.x*128 + tid;
    int type = gid >> 16;              // 0=q, 1=k, 2=v (uniform per block)
    int rem  = gid & 0xFFFF;
    int head = rem >> 15;              // 0 or 1
    int tok  = rem & (NTOK-1);
    int b = tok >> 11;
    int t = tok & (NT-1);

    float xr[NC];
    if (fuse_embed){
        int id = idx[tok];
        const float4* t4 = (const float4*)te + id*4;
        const float4* p4 = (const float4*)pe + t*4;
        bool wr = (type==0) && (head==0);
        #pragma unroll
        for (int k=0;k<4;k++){
            float4 aa=t4[k], bb=p4[k];
            float4 r = make_float4(aa.x+bb.x, aa.y+bb.y, aa.z+bb.z, aa.w+bb.w);
            if (wr) ((float4*)g_x)[(size_t)tok*4 + k] = r;  // write once
            xr[4*k]=r.x; xr[4*k+1]=r.y; xr[4*k+2]=r.z; xr[4*k+3]=r.w;
        }
    } else {
        const float4* x4 = (const float4*)g_x + (size_t)tok*4;
        #pragma unroll
        for (int k=0;k<4;k++){
            float4 v=x4[k];
            xr[4*k]=v.x; xr[4*k+1]=v.y; xr[4*k+2]=v.z; xr[4*k+3]=v.w;
        }
    }

    float m=0.f;
    #pragma unroll
    for (int c=0;c<NC;c++) m += xr[c];
    m *= (1.f/NC);
    float var=0.f;
    #pragma unroll
    for (int c=0;c<NC;c++){ float d=xr[c]-m; var += d*d; }
    var *= (1.f/NC);
    float inv = rsqrtf(var + EPSF);
    float h[NC];
    #pragma unroll
    for (int c=0;c<NC;c++) h[c] = (xr[c]-m)*inv*sg[c] + sb[c];

    const float* W = (type==0 ? sq : (type==1 ? sk : sv)) + head*NC*NHS;
    float acc[NHS];
    #pragma unroll
    for (int s=0;s<NHS;s++) acc[s]=0.f;
    #pragma unroll
    for (int c=0;c<NC;c++){
        float hc = h[c];
        #pragma unroll
        for (int s=0;s<NHS;s++) acc[s] += hc*W[c*NHS+s];
    }
    float scale = (type==0) ? QSCALE : 1.f;
    size_t obase = ((size_t)(b*NH+head)*NT + t)*NHS;
    float* dst = (type==0 ? g_q : (type==1 ? g_k : g_v)) + obase;
    ((float4*)dst)[0] = make_float4(acc[0]*scale, acc[1]*scale, acc[2]*scale, acc[3]*scale);
    ((float4*)dst)[1] = make_float4(acc[4]*scale, acc[5]*scale, acc[6]*scale, acc[7]*scale);
}

// ---------------------------------------------------------------------------
// 2) Causal attention, split-K mod-4 + dual-query + key-pair packed smem.
//    Smem layout: kq[jj*10 + c] = (k_{2jj}[c], k_{2jj+1}[c]) as f32 pair
//    (stride 10 u64 keeps LDS.128 16B-aligned and STS near conflict-free).
//    Scores come out key-pair packed -> no per-key horizontal fold.
// ---------------------------------------------------------------------------
#define SCORE8(dst, q, kA, kB, kC, kD) \
    u64 dst = mul2(q[0], kA.x); \
    dst = fma2(q[1], kA.y, dst); \
    dst = fma2(q[2], kB.x, dst); \
    dst = fma2(q[3], kB.y, dst); \
    dst = fma2(q[4], kC.x, dst); \
    dst = fma2(q[5], kC.y, dst); \
    dst = fma2(q[6], kD.x, dst); \
    dst = fma2(q[7], kD.y, dst);

#define ACCUM8(acc, p, vA, vB, vC, vD) \
    acc[0]=fma2(p, vA.x, acc[0]); acc[1]=fma2(p, vA.y, acc[1]); \
    acc[2]=fma2(p, vB.x, acc[2]); acc[3]=fma2(p, vB.y, acc[3]); \
    acc[4]=fma2(p, vC.x, acc[4]); acc[5]=fma2(p, vC.y, acc[5]); \
    acc[6]=fma2(p, vD.x, acc[6]); acc[7]=fma2(p, vD.y, acc[7]);

__global__ void __launch_bounds__(128) attn_kernel(){
    int bh   = blockIdx.x;
    int a    = blockIdx.y;              // 0..7
    int s    = blockIdx.z;              // key-tile residue mod 4
    int lane = threadIdx.x;             // 0..127
    int b = 15 - a;

    const float4* kg = (const float4*)g_k + (size_t)bh*NT*2;
    const float4* vg = (const float4*)g_v + (size_t)bh*NT*2;

    int tA = a*128 + lane;
    int tB = b*128 + lane;

    u64 qa[8], qb[8];
    {
        const float4* qp = (const float4*)(g_q + ((size_t)bh*NT + tA)*NHS);
        float4 q0 = qp[0], q1 = qp[1];
        qa[0]=pack2(q0.x,q0.x); qa[1]=pack2(q0.y,q0.y);
        qa[2]=pack2(q0.z,q0.z); qa[3]=pack2(q0.w,q0.w);
        qa[4]=pack2(q1.x,q1.x); qa[5]=pack2(q1.y,q1.y);
        qa[6]=pack2(q1.z,q1.z); qa[7]=pack2(q1.w,q1.w);
        const float4* qq = (const float4*)(g_q + ((size_t)bh*NT + tB)*NHS);
        float4 r0 = qq[0], r1 = qq[1];
        qb[0]=pack2(r0.x,r0.x); qb[1]=pack2(r0.y,r0.y);
        qb[2]=pack2(r0.z,r0.z); qb[3]=pack2(r0.w,r0.w);
        qb[4]=pack2(r1.x,r1.x); qb[5]=pack2(r1.y,r1.y);
        qb[6]=pack2(r1.z,r1.z); qb[7]=pack2(r1.w,r1.w);
    }

    __shared__ u64 kq[64*10];   // 5120 B, key-pair packed
    __shared__ u64 vq[64*10];

    u64 accA[8], accB[8];
    #pragma unroll
    for (int c=0;c<8;c++){ accA[c]=0ull; accB[c]=0ull; }
    u64 denA2 = 0ull, denB2 = 0ull;

    for (int kt=s; kt<=b; kt+=NSPLIT){
        // stage: thread = one key; write 8 dims into pair layout (2 halves)
        {
            float4 f0 = kg[kt*256 + lane*2];
            float4 f1 = kg[kt*256 + lane*2 + 1];
            float4 h0 = vg[kt*256 + lane*2];
            float4 h1 = vg[kt*256 + lane*2 + 1];
            int jp = lane>>1, jl = lane&1;
            float* kb = (float*)(kq + jp*10) + jl;
            kb[0]=f0.x; kb[2]=f0.y; kb[4]=f0.z; kb[6]=f0.w;
            kb[8]=f1.x; kb[10]=f1.y; kb[12]=f1.z; kb[14]=f1.w;
            float* vb = (float*)(vq + jp*10) + jl;
            vb[0]=h0.x; vb[2]=h0.y; vb[4]=h0.z; vb[6]=h0.w;
            vb[8]=h1.x; vb[10]=h1.y; vb[12]=h1.z; vb[14]=h1.w;
        }
        __syncthreads();

        if (kt < a){
            // dual clean
            #pragma unroll 2
            for (int jj=0; jj<64; jj++){
                const ulonglong2* kp = (const ulonglong2*)(kq + jj*10);
                ulonglong2 kA=kp[0], kB=kp[1], kC=kp[2], kD=kp[3];
                SCORE8(sA, qa, kA,kB,kC,kD);
                SCORE8(sB, qb, kA,kB,kC,kD);
                float2 fa=unpack2(sA), fb=unpack2(sB);
                u64 pA = pack2(ex2f(fa.x), ex2f(fa.y));
                u64 pB = pack2(ex2f(fb.x), ex2f(fb.y));
                denA2 = add2(denA2, pA); denB2 = add2(denB2, pB);
                const ulonglong2* vp = (const ulonglong2*)(vq + jj*10);
                ulonglong2 vA=vp[0], vB=vp[1], vC=vp[2], vD=vp[3];
                ACCUM8(accA, pA, vA,vB,vC,vD);
                ACCUM8(accB, pB, vA,vB,vC,vD);
            }
        } else if (kt == a){
            // dual, A diag-masked
            #pragma unroll 2
            for (int jj=0; jj<64; jj++){
                const ulonglong2* kp = (const ulonglong2*)(kq + jj*10);
                ulonglong2 kA=kp[0], kB=kp[1], kC=kp[2], kD=kp[3];
                SCORE8(sA, qa, kA,kB,kC,kD);
                SCORE8(sB, qb, kA,kB,kC,kD);
                float2 fa=unpack2(sA), fb=unpack2(sB);
                float pa0 = ex2f(fa.x); if (2*jj   > lane) pa0 = 0.f;
                float pa1 = ex2f(fa.y); if (2*jj+1 > lane) pa1 = 0.f;
                u64 pA = pack2(pa0, pa1);
                u64 pB = pack2(ex2f(fb.x), ex2f(fb.y));
                denA2 = add2(denA2, pA); denB2 = add2(denB2, pB);
                const ulonglong2* vp = (const ulonglong2*)(vq + jj*10);
                ulonglong2 vA=vp[0], vB=vp[1], vC=vp[2], vD=vp[3];
                ACCUM8(accA, pA, vA,vB,vC,vD);
                ACCUM8(accB, pB, vA,vB,vC,vD);
            }
        } else if (kt < b){
            // single clean (B only)
            #pragma unroll 4
            for (int jj=0; jj<64; jj++){
                const ulonglong2* kp = (const ulonglong2*)(kq + jj*10);
                ulonglong2 kA=kp[0], kB=kp[1], kC=kp[2], kD=kp[3];
                SCORE8(sB, qb, kA,kB,kC,kD);
                float2 fb=unpack2(sB);
                u64 pB = pack2(ex2f(fb.x), ex2f(fb.y));
                denB2 = add2(denB2, pB);
                const ulonglong2* vp = (const ulonglong2*)(vq + jj*10);
                ulonglong2 vA=vp[0], vB=vp[1], vC=vp[2], vD=vp[3];
                ACCUM8(accB, pB, vA,vB,vC,vD);
            }
        } else {
            // single diag (kt == b)
            int jje = lane>>1;
            #pragma unroll 4
            for (int jj=0; jj<jje; jj++){
                const ulonglong2* kp = (const ulonglong2*)(kq + jj*10);
                ulonglong2 kA=kp[0], kB=kp[1], kC=kp[2], kD=kp[3];
                SCORE8(sB, qb, kA,kB,kC,kD);
                float2 fb=unpack2(sB);
                u64 pB = pack2(ex2f(fb.x), ex2f(fb.y));
                denB2 = add2(denB2, pB);
                const ulonglong2* vp = (const ulonglong2*)(vq + jj*10);
                ulonglong2 vA=vp[0], vB=vp[1], vC=vp[2], vD=vp[3];
                ACCUM8(accB, pB, vA,vB,vC,vD);
            }
            {   // tail jj = jje: key 2*jje (= lane&~1) valid; key 2*jje+1 valid iff lane odd
                int jj = jje;
                const ulonglong2* kp = (const ulonglong2*)(kq + jj*10);
                ulonglong2 kA=kp[0], kB=kp[1], kC=kp[2], kD=kp[3];
                SCORE8(sB, qb, kA,kB,kC,kD);
                float2 fb=unpack2(sB);
                float pb0 = ex2f(fb.x);
                float pb1 = (lane & 1) ? ex2f(fb.y) : 0.f;
                u64 pB = pack2(pb0, pb1);
                denB2 = add2(denB2, pB);
                const ulonglong2* vp = (const ulonglong2*)(vq + jj*10);
                ulonglong2 vA=vp[0], vB=vp[1], vC=vp[2], vD=vp[3];
                ACCUM8(accB, pB, vA,vB,vC,vD);
            }
        }
        __syncthreads();
    }

    // write unnormalized partials (fold key-pair accumulators once)
    int pAi = bh*NT + tA;
    int pBi = bh*NT + tB;
    {
        float2 d = unpack2(denA2);
        g_pden[s*NQ + pAi] = d.x + d.y;
        float r[8];
        #pragma unroll
        for (int c=0;c<8;c++){ float2 f=unpack2(accA[c]); r[c]=f.x+f.y; }
        float4* op = (float4*)(g_pacc + ((size_t)s*NQ + pAi)*NHS);
        op[0] = make_float4(r[0],r[1],r[2],r[3]);
        op[1] = make_float4(r[4],r[5],r[6],r[7]);
    }
    {
        float2 d = unpack2(denB2);
        g_pden[s*NQ + pBi] = d.x + d.y;
        float r[8];
        #pragma unroll
        for (int c=0;c<8;c++){ float2 f=unpack2(accB[c]); r[c]=f.x+f.y; }
        float4* op = (float4*)(g_pacc + ((size_t)s*NQ + pBi)*NHS);
        op[0] = make_float4(r[0],r[1],r[2],r[3]);
        op[1] = make_float4(r[4],r[5],r[6],r[7]);
    }
}

// ---------------------------------------------------------------------------
// 3) combine(splits) fused: o = Σacc/Σden; then x += o @ Wo^T; h = LN2(x);
//    x += relu(h @ W1^T) @ W2^T. One thread per token (R7 structure).
// ---------------------------------------------------------------------------
__global__ void __launch_bounds__(128) post_kernel(const float* __restrict__ wo,
                            const float* __restrict__ g2,
                            const float* __restrict__ b2,
                            const float* __restrict__ w1,
                            const float* __restrict__ w2){
    __shared__ __align__(16) float s_wo[NC*NC];
    __shared__ __align__(16) float s_w1[4*NC*NC];
    __shared__ __align__(16) float s_w2[4*NC*NC];   // [j][i] = w2[i][j]
    __shared__ float sg[NC], sb[NC];
    int tid = threadIdx.x;
    for (int i=tid; i<NC*NC; i+=128) s_wo[i] = wo[i];
    for (int i=tid; i<4*NC*NC; i+=128) s_w1[i] = w1[i];
    for (int idx=tid; idx<4*NC*NC; idx+=128){
        int j = idx >> 4, i = idx & 15;
        s_w2[idx] = w2[i*(4*NC) + j];
    }
    if (tid < NC){ sg[tid]=g2[tid]; sb[tid]=b2[tid]; }
    __syncthreads();

    int tok = blockIdx.x*128 + tid;
    int b = tok >> 11;
    int t = tok & (NT-1);
    int p0 = (b*NH+0)*NT + t;
    int p1 = (b*NH+1)*NT + t;

    // fused combine: o = (Σ_s acc_s) / (Σ_s den_s) per head
    float den0 = 0.f, den1 = 0.f;
    #pragma unroll
    for (int s=0;s<NSPLIT;s++){ den0 += g_pden[s*NQ + p0]; den1 += g_pden[s*NQ + p1]; }
    float4 a00=make_float4(0,0,0,0), a01=make_float4(0,0,0,0);
    float4 a10=make_float4(0,0,0,0), a11=make_float4(0,0,0,0);
    #pragma unroll
    for (int s=0;s<NSPLIT;s++){
        const float4* q0 = (const float4*)(g_pacc + ((size_t)s*NQ + p0)*NHS);
        float4 x0=q0[0], x1=q0[1];
        a00.x+=x0.x; a00.y+=x0.y; a00.z+=x0.z; a00.w+=x0.w;
        a01.x+=x1.x; a01.y+=x1.y; a01.z+=x1.z; a01.w+=x1.w;
        const float4* q1 = (const float4*)(g_pacc + ((size_t)s*NQ + p1)*NHS);
        float4 y0=q1[0], y1=q1[1];
        a10.x+=y0.x; a10.y+=y0.y; a10.z+=y0.z; a10.w+=y0.w;
        a11.x+=y1.x; a11.y+=y1.y; a11.z+=y1.z; a11.w+=y1.w;
    }
    float i0 = 1.f/den0, i1 = 1.f/den1;
    u64 o2[8];
    o2[0] = pack2(a00.x*i0, a00.y*i0);
    o2[1] = pack2(a00.z*i0, a00.w*i0);
    o2[2] = pack2(a01.x*i0, a01.y*i0);
    o2[3] = pack2(a01.z*i0, a01.w*i0);
    o2[4] = pack2(a10.x*i1, a10.y*i1);
    o2[5] = pack2(a10.z*i1, a10.w*i1);
    o2[6] = pack2(a11.x*i1, a11.y*i1);
    o2[7] = pack2(a11.z*i1, a11.w*i1);

    float xr[NC];
    {
        const float4* x4 = (const float4*)g_x + (size_t)tok*4;
        #pragma unroll
        for (int k=0;k<4;k++){
            float4 v=x4[k];
            xr[4*k]=v.x; xr[4*k+1]=v.y; xr[4*k+2]=v.z; xr[4*k+3]=v.w;
        }
    }

    // Wo projection + residual (f32x2)
    #pragma unroll
    for (int i=0;i<NC;i++){
        const ulonglong2* wr = (const ulonglong2*)(s_wo + i*NC);
        ulonglong2 w0 = wr[0], w1r = wr[1];
        u64 s2 = mul2(o2[0], w0.x);
        s2 = fma2(o2[1], w0.y, s2);
        s2 = fma2(o2[2], w1r.x, s2);
        s2 = fma2(o2[3], w1r.y, s2);
        ulonglong2 w2r = wr[2], w3r = wr[3];
        s2 = fma2(o2[4], w2r.x, s2);
        s2 = fma2(o2[5], w2r.y, s2);
        s2 = fma2(o2[6], w3r.x, s2);
        s2 = fma2(o2[7], w3r.y, s2);
        float2 f = unpack2(s2);
        xr[i] += f.x + f.y;
    }

    // LN2
    float m=0.f;
    #pragma unroll
    for (int c=0;c<NC;c++) m += xr[c];
    m *= (1.f/NC);
    float var=0.f;
    #pragma unroll
    for (int c=0;c<NC;c++){ float d=xr[c]-m; var += d*d; }
    var *= (1.f/NC);
    float inv = rsqrtf(var + EPSF);
    u64 hp[8];
    #pragma unroll
    for (int c=0;c<NC;c+=2){
        float h0 = (xr[c]-m)*inv*sg[c] + sb[c];
        float h1 = (xr[c+1]-m)*inv*sg[c+1] + sb[c+1];
        hp[c>>1] = pack2(h0, h1);
    }

    // MLP (f32x2)
    u64 d0=0,d1=0,d2=0,d3=0,d4=0,d5=0,d6=0,d7=0;
    #pragma unroll 4
    for (int j=0;j<4*NC;j++){
        const ulonglong2* wr = (const ulonglong2*)(s_w1 + j*NC);
        ulonglong2 a0 = wr[0], a1 = wr[1], a2 = wr[2], a3 = wr[3];
        u64 y2 = mul2(hp[0], a0.x);
        y2 = fma2(hp[1], a0.y, y2);
        y2 = fma2(hp[2], a1.x, y2);
        y2 = fma2(hp[3], a1.y, y2);
        y2 = fma2(hp[4], a2.x, y2);
        y2 = fma2(hp[5], a2.y, y2);
        y2 = fma2(hp[6], a3.x, y2);
        y2 = fma2(hp[7], a3.y, y2);
        float2 yf = unpack2(y2);
        float yv = fmaxf(yf.x + yf.y, 0.f);
        u64 yy = pack2(yv, yv);
        const ulonglong2* cr = (const ulonglong2*)(s_w2 + j*NC);
        ulonglong2 c0 = cr[0], c1 = cr[1], c2 = cr[2], c3 = cr[3];
        d0 = fma2(yy, c0.x, d0);
        d1 = fma2(yy, c0.y, d1);
        d2 = fma2(yy, c1.x, d2);
        d3 = fma2(yy, c1.y, d3);
        d4 = fma2(yy, c2.x, d4);
        d5 = fma2(yy, c2.y, d5);
        d6 = fma2(yy, c3.x, d6);
        d7 = fma2(yy, c3.y, d7);
    }
    float2 e0=unpack2(d0), e1=unpack2(d1), e2=unpack2(d2), e3=unpack2(d3);
    float2 e4=unpack2(d4), e5=unpack2(d5), e6=unpack2(d6), e7=unpack2(d7);
    xr[0]+=e0.x; xr[1]+=e0.y; xr[2]+=e1.x; xr[3]+=e1.y;
    xr[4]+=e2.x; xr[5]+=e2.y; xr[6]+=e3.x; xr[7]+=e3.y;
    xr[8]+=e4.x; xr[9]+=e4.y; xr[10]+=e5.x; xr[11]+=e5.y;
    xr[12]+=e6.x; xr[13]+=e6.y; xr[14]+=e7.x; xr[15]+=e7.y;

    float4* xo = (float4*)g_x + (size_t)tok*4;
    #pragma unroll
    for (int k=0;k<4;k++)
        xo[k] = make_float4(xr[4*k], xr[4*k+1], xr[4*k+2], xr[4*k+3]);
}

// ---------------------------------------------------------------------------
// 4) h = LNf(x); logits = h @ tok_emb^T.
//    Block = 256 threads, 16 tokens/block; te row registered once per thread.
// ---------------------------------------------------------------------------
__global__ void __launch_bounds__(NV) head_kernel(const float* __restrict__ te,
                                                  const float* __restrict__ gf,
                                                  const float* __restrict__ bf,
                                                  float* __restrict__ out){
    int tid  = threadIdx.x;
    int warp = tid >> 5, lane = tid & 31;
    int tok0 = blockIdx.x * 16;
    __shared__ __align__(16) float hs[16][NC];

    {
        int sub = lane >> 4;           // 0 or 1
        int c   = lane & 15;
        int tok = tok0 + warp*2 + sub;
        float val = g_x[(size_t)tok*NC + c];
        float s = val;
        #pragma unroll
        for (int o=8;o>0;o>>=1) s += __shfl_xor_sync(0xffffffffu, s, o, 16);
        float m = s * (1.f/NC);
        float d = val - m;
        float vv = d*d;
        #pragma unroll
        for (int o=8;o>0;o>>=1) vv += __shfl_xor_sync(0xffffffffu, vv, o, 16);
        float inv = rsqrtf(vv*(1.f/NC) + EPSF);
        hs[warp*2+sub][c] = d*inv*gf[c] + bf[c];
    }
    __syncthreads();

    int v = tid;
    const ulonglong2* tr = (const ulonglong2*)te + v*4;
    ulonglong2 t0 = tr[0], t1 = tr[1], t2 = tr[2], t3 = tr[3];

    #pragma unroll 4
    for (int k=0;k<16;k++){
        const ulonglong2* hp = (const ulonglong2*)hs[k];
        ulonglong2 h0 = hp[0], h1 = hp[1];
        u64 s2 = mul2(h0.x, t0.x);
        s2 = fma2(h0.y, t0.y, s2);
        s2 = fma2(h1.x, t1.x, s2);
        s2 = fma2(h1.y, t1.y, s2);
        ulonglong2 h2 = hp[2], h3 = hp[3];
        s2 = fma2(h2.x, t2.x, s2);
        s2 = fma2(h2.y, t2.y, s2);
        s2 = fma2(h3.x, t3.x, s2);
        s2 = fma2(h3.y, t3.y, s2);
        float2 f = unpack2(s2);
        out[(size_t)(tok0+k)*NV + v] = f.x + f.y;
    }
}

// ---------------------------------------------------------------------------
extern "C" void kernel_launch(void* const* d_in, const int* in_sizes, int n_in,
                              void* d_out, int out_size){
    const int*   idx  = (const int*)  d_in[0];
    const float* te   = (const float*)d_in[1];
    const float* pe   = (const float*)d_in[2];
    const float* wq   = (const float*)d_in[3];
    const float* wk   = (const float*)d_in[4];
    const float* wv   = (const float*)d_in[5];
    const float* wo   = (const float*)d_in[6];
    const float* ln1g = (const float*)d_in[7];
    const float* ln1b = (const float*)d_in[8];
    const float* ln2g = (const float*)d_in[9];
    const float* ln2b = (const float*)d_in[10];
    const float* w1   = (const float*)d_in[11];
    const float* w2   = (const float*)d_in[12];
    const float* lnfg = (const float*)d_in[13];
    const float* lnfb = (const float*)d_in[14];
    float* out = (float*)d_out;

    for (int l=0; l<NL; l++){
        qkv_kernel<<<NTOK*NH*3/128, 128>>>(wq + l*NH*NC*NHS, wk + l*NH*NC*NHS,
                                           wv + l*NH*NC*NHS, ln1g + l*NC, ln1b + l*NC,
                                           idx, te, pe, (l==0) ? 1 : 0);
        dim3 ag(NB*NH, 8, NSPLIT);
        attn_kernel<<<ag, 128>>>();
        post_kernel<<<NTOK/128, 128>>>(wo + l*NC*NC, ln2g + l*NC, ln2b + l*NC,
                                       w1 + l*4*NC*NC, w2 + l*4*NC*NC);
    }
    head_kernel<<<NTOK/16, NV>>>(te, lnfg, lnfb, out);
}